// round 6
// baseline (speedup 1.0000x reference)
#include <cuda_runtime.h>
#include <cuda_bf16.h>
#include <cstdint>

// Problem constants
#define BATCH     4
#define SEQ       1024
#define EMB       1024
#define NHEADS    16
#define HDIM      64
#define QKV_COLS  (3 * NHEADS * HDIM)   // 3072
#define ROWS      (BATCH * SEQ)         // 4096

// Scratch (allocation-free rule: __device__ globals)
__device__ float g_qkv[ROWS * QKV_COLS];        // 4096 x 3072 (tf32-rounded)
__device__ float g_att[ROWS * EMB];             // 4096 x 1024 (tf32-rounded)
__device__ float g_xr[ROWS * EMB];              // tf32-rounded x
__device__ float g_wqkvr[EMB * QKV_COLS];       // tf32-rounded W_qkv
__device__ float g_woutr[EMB * EMB];            // tf32-rounded W_out

__device__ __forceinline__ uint32_t f2tf32(float x) {
    uint32_t u;
    asm("cvt.rna.tf32.f32 %0, %1;" : "=r"(u) : "f"(x));
    return u;
}
__device__ __forceinline__ float f2tf32f(float x) {
    return __uint_as_float(f2tf32(x));
}

__device__ __forceinline__ void mma_tf32(float c[4], const uint32_t a[4], const uint32_t b[2]) {
    asm volatile(
        "mma.sync.aligned.m16n8k8.row.col.f32.tf32.tf32.f32 "
        "{%0,%1,%2,%3},{%4,%5,%6,%7},{%8,%9},{%0,%1,%2,%3};"
        : "+f"(c[0]), "+f"(c[1]), "+f"(c[2]), "+f"(c[3])
        : "r"(a[0]), "r"(a[1]), "r"(a[2]), "r"(a[3]), "r"(b[0]), "r"(b[1]));
}

__device__ __forceinline__ void cp_async16(uint32_t dst, const void* src) {
    asm volatile("cp.async.cg.shared.global [%0], [%1], 16;" :: "r"(dst), "l"(src));
}
__device__ __forceinline__ void cp_commit() {
    asm volatile("cp.async.commit_group;");
}
template <int N>
__device__ __forceinline__ void cp_wait() {
    asm volatile("cp.async.wait_group %0;" :: "n"(N));
}

// ===========================================================================
// Prepass: tf32-round three tensors (float4 grid-stride)
// ===========================================================================
__global__ void round_prepass(const float4* __restrict__ s0, float4* __restrict__ d0, int n0,
                              const float4* __restrict__ s1, float4* __restrict__ d1, int n1,
                              const float4* __restrict__ s2, float4* __restrict__ d2, int n2)
{
    const int total = n0 + n1 + n2;   // in float4 units
    for (int i = blockIdx.x * blockDim.x + threadIdx.x; i < total;
         i += gridDim.x * blockDim.x) {
        const float4* s; float4* d; int j = i;
        if (j < n0)            { s = s0; d = d0; }
        else if ((j -= n0) < n1) { s = s1; d = d1; }
        else                   { j -= n1; s = s2; d = d2; }
        float4 v = s[j];
        v.x = f2tf32f(v.x); v.y = f2tf32f(v.y);
        v.z = f2tf32f(v.z); v.w = f2tf32f(v.w);
        d[j] = v;
    }
}

// ===========================================================================
// TF32 mma.sync GEMM, fused bias. Operands are PRE-ROUNDED tf32 bits; no
// cvt anywhere in the loop (pure LDS + HMMA). Optional rounding of output.
// CTA 128x128x32, 8 warps, cp.async 2-stage, 2 CTAs/SM.
// ===========================================================================
#define GBM 128
#define GBN 128
#define GBK 32
#define ASTRIDE 36
#define BSTRIDE 136
#define ABUF (GBM * ASTRIDE)
#define BBUF (GBK * BSTRIDE)
#define GEMM_SMEM ((2 * ABUF + 2 * BBUF) * 4)   // 71680 bytes

template <bool ROUND_STORE>
__global__ __launch_bounds__(256, 2) void mma_gemm_bias(
    int M, int N, int K,
    const float* __restrict__ A,
    const float* __restrict__ B,
    const float* __restrict__ bias,
    float* __restrict__ C)
{
    extern __shared__ float smf[];
    float* As = smf;                 // [2][GBM][ASTRIDE]
    float* Bs = smf + 2 * ABUF;      // [2][GBK][BSTRIDE]
    const uint32_t sAs = (uint32_t)__cvta_generic_to_shared(As);
    const uint32_t sBs = (uint32_t)__cvta_generic_to_shared(Bs);

    const int t    = threadIdx.x;
    const int lane = t & 31;
    const int warp = t >> 5;
    const int wm   = warp >> 2;
    const int wn   = warp & 3;
    const int grp  = lane >> 2;
    const int qid  = lane & 3;

    const int bm = blockIdx.y * GBM;
    const int bn = blockIdx.x * GBN;

    const int arow = t >> 3;
    const int acol = (t & 7) * 4;
    const int brow = t >> 5;
    const int bcol = (t & 31) * 4;

    auto issue = [&](int buf, int kt) {
        const float* Ag = A + (size_t)bm * K + kt * GBK;
        const float* Bg = B + (size_t)(kt * GBK) * N + bn;
        #pragma unroll
        for (int p = 0; p < 4; p++) {
            int r = arow + p * 32;
            cp_async16(sAs + (uint32_t)(buf * ABUF + r * ASTRIDE + acol) * 4,
                       &Ag[(size_t)r * K + acol]);
        }
        #pragma unroll
        for (int p = 0; p < 4; p++) {
            int r = brow + p * 8;
            cp_async16(sBs + (uint32_t)(buf * BBUF + r * BSTRIDE + bcol) * 4,
                       &Bg[(size_t)r * N + bcol]);
        }
    };

    float c[4][4][4];
    #pragma unroll
    for (int mi = 0; mi < 4; mi++)
        #pragma unroll
        for (int ni = 0; ni < 4; ni++)
            #pragma unroll
            for (int r = 0; r < 4; r++)
                c[mi][ni][r] = 0.0f;

    issue(0, 0);
    cp_commit();

    const int NT = K / GBK;
    for (int kt = 0; kt < NT; kt++) {
        const int cur = kt & 1;
        if (kt + 1 < NT) {
            issue(cur ^ 1, kt + 1);
            cp_commit();
            cp_wait<1>();
        } else {
            cp_wait<0>();
        }
        __syncthreads();

        const float* Ab = As + cur * ABUF + (wm * 64) * ASTRIDE;
        const float* Bb = Bs + cur * BBUF + wn * 32;

        #pragma unroll
        for (int ks = 0; ks < 4; ks++) {
            const int kb = ks * 8;
            uint32_t af[4][4], bf[4][2];
            #pragma unroll
            for (int mi = 0; mi < 4; mi++) {
                const float* ap = Ab + (mi * 16 + grp) * ASTRIDE + kb + qid;
                af[mi][0] = __float_as_uint(ap[0]);
                af[mi][1] = __float_as_uint(ap[8 * ASTRIDE]);
                af[mi][2] = __float_as_uint(ap[4]);
                af[mi][3] = __float_as_uint(ap[8 * ASTRIDE + 4]);
            }
            #pragma unroll
            for (int ni = 0; ni < 4; ni++) {
                const float* bp = Bb + (kb + qid) * BSTRIDE + ni * 8 + grp;
                bf[ni][0] = __float_as_uint(bp[0]);
                bf[ni][1] = __float_as_uint(bp[4 * BSTRIDE]);
            }
            #pragma unroll
            for (int mi = 0; mi < 4; mi++)
                #pragma unroll
                for (int ni = 0; ni < 4; ni++)
                    mma_tf32(c[mi][ni], af[mi], bf[ni]);
        }
        __syncthreads();
    }

    #pragma unroll
    for (int mi = 0; mi < 4; mi++) {
        const int r0 = bm + wm * 64 + mi * 16 + grp;
        #pragma unroll
        for (int ni = 0; ni < 4; ni++) {
            const int col = bn + wn * 32 + ni * 8 + qid * 2;
            float2 bv = *(const float2*)&bias[col];
            float2 v0, v1;
            v0.x = c[mi][ni][0] + bv.x;  v0.y = c[mi][ni][1] + bv.y;
            v1.x = c[mi][ni][2] + bv.x;  v1.y = c[mi][ni][3] + bv.y;
            if (ROUND_STORE) {
                v0.x = f2tf32f(v0.x); v0.y = f2tf32f(v0.y);
                v1.x = f2tf32f(v1.x); v1.y = f2tf32f(v1.y);
            }
            *(float2*)&C[(size_t)r0 * N + col]       = v0;
            *(float2*)&C[(size_t)(r0 + 8) * N + col] = v1;
        }
    }
}

// ===========================================================================
// Tensor-core flash attention (tf32 mma). Inputs in g_qkv are PRE-ROUNDED,
// so K/V/Q staging has no cvts. Output written tf32-rounded for out-proj.
// ===========================================================================
#define AKT 64
#define ASTR 68
#define ATT_SMEM ((2 * AKT * ASTR + 128 * ASTR) * 4)   // 69632 bytes

__global__ __launch_bounds__(256, 2) void attn_mma_kernel()
{
    extern __shared__ float smaf[];
    float* Ks = smaf;                  // [64][ASTR]
    float* Vt = smaf + AKT * ASTR;     // [64][ASTR]  (Vt[d][j] = V[j][d])
    float* Ps = smaf + 2 * AKT * ASTR; // [128][ASTR] (also Q staging)

    const int t    = threadIdx.x;
    const int lane = t & 31;
    const int warp = t >> 5;
    const int g8   = lane >> 2;
    const int qid  = lane & 3;

    const int bh = blockIdx.y;
    const int b  = bh >> 4;
    const int h  = bh & 15;
    const int hoff  = h * HDIM;
    const int qrow0 = blockIdx.x * 128;

    const size_t rowStride = QKV_COLS;
    const float* Kg = g_qkv + (size_t)b * SEQ * rowStride + hoff;              // K third
    const float* Vg = Kg + 2 * EMB;                                            // V third
    const float* Qg = g_qkv + ((size_t)b * SEQ + qrow0) * rowStride + EMB + hoff;

    // ---- stage Q (x0.125 exact exponent shift) ----
    {
        const int j     = t >> 1;
        const int cbase = (t & 1) * 32;
        #pragma unroll
        for (int p = 0; p < 8; p++) {
            float4 v = *(const float4*)&Qg[(size_t)j * rowStride + cbase + p * 4];
            v.x *= 0.125f; v.y *= 0.125f; v.z *= 0.125f; v.w *= 0.125f;
            *(float4*)&Ps[j * ASTR + cbase + p * 4] = v;
        }
    }
    __syncthreads();

    // ---- load Q fragments ----
    uint32_t qa[8][4];
    {
        const float* Qw = Ps + (warp * 16 + g8) * ASTR;
        #pragma unroll
        for (int ks = 0; ks < 8; ks++) {
            const float* ap = Qw + ks * 8 + qid;
            qa[ks][0] = __float_as_uint(ap[0]);
            qa[ks][1] = __float_as_uint(ap[8 * ASTR]);
            qa[ks][2] = __float_as_uint(ap[4]);
            qa[ks][3] = __float_as_uint(ap[8 * ASTR + 4]);
        }
    }
    __syncthreads();

    float oc[8][4];
    #pragma unroll
    for (int ni = 0; ni < 8; ni++)
        #pragma unroll
        for (int r = 0; r < 4; r++) oc[ni][r] = 0.0f;
    float lsum0 = 0.0f, lsum1 = 0.0f;

    const int vj = t & 63;
    const int vc = (t >> 6) * 4;

    for (int kt = 0; kt < SEQ / AKT; kt++) {
        const float* Kn = Kg + (size_t)kt * AKT * rowStride;
        const float* Vn = Vg + (size_t)kt * AKT * rowStride;
        #pragma unroll
        for (int p = 0; p < 4; p++) {
            int e = t + p * 256;
            int j = e >> 4, c4 = (e & 15) * 4;
            *(float4*)&Ks[j * ASTR + c4] =
                *(const float4*)&Kn[(size_t)j * rowStride + c4];
        }
        #pragma unroll
        for (int p = 0; p < 4; p++) {
            int d = vc + p * 16;
            float4 v = *(const float4*)&Vn[(size_t)vj * rowStride + d];
            Vt[(d + 0) * ASTR + vj] = v.x;
            Vt[(d + 1) * ASTR + vj] = v.y;
            Vt[(d + 2) * ASTR + vj] = v.z;
            Vt[(d + 3) * ASTR + vj] = v.w;
        }
        __syncthreads();

        // ---- S = Q K^T ----
        float sc[8][4];
        #pragma unroll
        for (int ni = 0; ni < 8; ni++)
            #pragma unroll
            for (int r = 0; r < 4; r++) sc[ni][r] = 0.0f;

        #pragma unroll
        for (int ks = 0; ks < 8; ks++) {
            uint32_t bf[8][2];
            #pragma unroll
            for (int ni = 0; ni < 8; ni++) {
                const float* bp = Ks + (ni * 8 + g8) * ASTR + ks * 8 + qid;
                bf[ni][0] = __float_as_uint(bp[0]);
                bf[ni][1] = __float_as_uint(bp[4]);
            }
            #pragma unroll
            for (int ni = 0; ni < 8; ni++)
                mma_tf32(sc[ni], qa[ks], bf[ni]);
        }

        // ---- P = exp(S); row-sum; store P (tf32-rounded) ----
        float* Pw = Ps + (warp * 16 + g8) * ASTR;
        #pragma unroll
        for (int ni = 0; ni < 8; ni++) {
            float p0 = __expf(sc[ni][0]);
            float p1 = __expf(sc[ni][1]);
            float p2 = __expf(sc[ni][2]);
            float p3 = __expf(sc[ni][3]);
            lsum0 += p0 + p1;
            lsum1 += p2 + p3;
            float2 u0, u1;
            u0.x = f2tf32f(p0); u0.y = f2tf32f(p1);
            u1.x = f2tf32f(p2); u1.y = f2tf32f(p3);
            *(float2*)&Pw[ni * 8 + qid * 2]            = u0;
            *(float2*)&Pw[8 * ASTR + ni * 8 + qid * 2] = u1;
        }
        __syncwarp();

        // ---- O += P V ----
        #pragma unroll
        for (int ks = 0; ks < 8; ks++) {
            uint32_t af[4];
            const float* ap = Pw + ks * 8 + qid;
            af[0] = __float_as_uint(ap[0]);
            af[1] = __float_as_uint(ap[8 * ASTR]);
            af[2] = __float_as_uint(ap[4]);
            af[3] = __float_as_uint(ap[8 * ASTR + 4]);
            uint32_t bf[8][2];
            #pragma unroll
            for (int ni = 0; ni < 8; ni++) {
                const float* bp = Vt + (ni * 8 + g8) * ASTR + ks * 8 + qid;
                bf[ni][0] = __float_as_uint(bp[0]);
                bf[ni][1] = __float_as_uint(bp[4]);
            }
            #pragma unroll
            for (int ni = 0; ni < 8; ni++)
                mma_tf32(oc[ni], af, bf[ni]);
        }
        __syncthreads();
    }

    // ---- normalize, round to tf32, write ----
    float l0 = lsum0, l1 = lsum1;
    #pragma unroll
    for (int m = 1; m < 4; m <<= 1) {
        l0 += __shfl_xor_sync(0xffffffffu, l0, m);
        l1 += __shfl_xor_sync(0xffffffffu, l1, m);
    }
    const float inv0 = 1.0f / l0;
    const float inv1 = 1.0f / l1;

    const int r0 = qrow0 + warp * 16 + g8;
    float* O0 = g_att + ((size_t)b * SEQ + r0) * EMB + hoff;
    float* O1 = O0 + 8 * EMB;
    #pragma unroll
    for (int ni = 0; ni < 8; ni++) {
        const int col = ni * 8 + qid * 2;
        float2 v0, v1;
        v0.x = f2tf32f(oc[ni][0] * inv0);  v0.y = f2tf32f(oc[ni][1] * inv0);
        v1.x = f2tf32f(oc[ni][2] * inv1);  v1.y = f2tf32f(oc[ni][3] * inv1);
        *(float2*)&O0[col] = v0;
        *(float2*)&O1[col] = v1;
    }
}

// ---------------------------------------------------------------------------
// Launch: inputs in order x, W_qkv, b_qkv, W_out, b_out
// ---------------------------------------------------------------------------
extern "C" void kernel_launch(void* const* d_in, const int* in_sizes, int n_in,
                              void* d_out, int out_size)
{
    const float* x     = (const float*)d_in[0];
    const float* W_qkv = (const float*)d_in[1];
    const float* b_qkv = (const float*)d_in[2];
    const float* W_out = (const float*)d_in[3];
    const float* b_out = (const float*)d_in[4];
    float*       out   = (float*)d_out;

    float *qkv_ptr, *att_ptr, *xr_ptr, *wqkvr_ptr, *woutr_ptr;
    cudaGetSymbolAddress((void**)&qkv_ptr,   g_qkv);
    cudaGetSymbolAddress((void**)&att_ptr,   g_att);
    cudaGetSymbolAddress((void**)&xr_ptr,    g_xr);
    cudaGetSymbolAddress((void**)&wqkvr_ptr, g_wqkvr);
    cudaGetSymbolAddress((void**)&woutr_ptr, g_woutr);

    static bool attr_set = false;
    if (!attr_set) {
        cudaFuncSetAttribute(mma_gemm_bias<true>,
                             cudaFuncAttributeMaxDynamicSharedMemorySize, GEMM_SMEM);
        cudaFuncSetAttribute(mma_gemm_bias<false>,
                             cudaFuncAttributeMaxDynamicSharedMemorySize, GEMM_SMEM);
        cudaFuncSetAttribute(attn_mma_kernel,
                             cudaFuncAttributeMaxDynamicSharedMemorySize, ATT_SMEM);
        attr_set = true;
    }

    // 0) Pre-round x, W_qkv, W_out to tf32
    round_prepass<<<1024, 256>>>(
        (const float4*)x,     (float4*)xr_ptr,    ROWS * EMB / 4,
        (const float4*)W_qkv, (float4*)wqkvr_ptr, EMB * QKV_COLS / 4,
        (const float4*)W_out, (float4*)woutr_ptr, EMB * EMB / 4);

    // 1) QKV projection (output tf32-rounded for attention)
    {
        dim3 grid(QKV_COLS / GBN, ROWS / GBM);   // (24, 32)
        mma_gemm_bias<true><<<grid, 256, GEMM_SMEM>>>(
            ROWS, QKV_COLS, EMB, xr_ptr, wqkvr_ptr, b_qkv, qkv_ptr);
    }

    // 2) Attention (tensor-core; output tf32-rounded for out-proj)
    {
        dim3 grid(SEQ / 128, BATCH * NHEADS);    // (8, 64)
        attn_mma_kernel<<<grid, 256, ATT_SMEM>>>();
    }

    // 3) Output projection (full fp32 output)
    {
        dim3 grid(EMB / GBN, ROWS / GBM);        // (8, 32)
        mma_gemm_bias<false><<<grid, 256, GEMM_SMEM>>>(
            ROWS, EMB, EMB, att_ptr, woutr_ptr, b_out, out);
    }
}